// round 2
// baseline (speedup 1.0000x reference)
#include <cuda_runtime.h>
#include <cuda_bf16.h>

#define EMBED 2048
#define FFN   8
#define MAXTOK 65536

// Intermediate q[N, FFN] scratch (2 MB). Static __device__ array: allocation-free.
__device__ float g_q[MAXTOK * FFN];

// ---------------------------------------------------------------------------
// Kernel 1: q[n,f] = cos^2( relu( x[n,:] . W1[f,:] + b1[f] ) )
// 256 threads/block; thread owns 8 contiguous embed elems; W1 slice in regs
// (64 regs/thread). Per token: 2x LDG.128 (prefetched 1 token ahead),
// 64 FFMA, 5-round butterfly reduce, 64-float smem partial, 8-thread finalize.
// ---------------------------------------------------------------------------
__global__ __launch_bounds__(256, 2)
void qff_gemm1(const float* __restrict__ x,
               const float* __restrict__ W1,
               const float* __restrict__ b1,
               int ntok)
{
    __shared__ float s_part[8][FFN];   // per-warp partial sums
    __shared__ float s_b1[FFN];

    const int tid = threadIdx.x;
    if (tid < FFN) s_b1[tid] = b1[tid];

    // Register-resident W1 slice: w1r[f][j] = W1[f, tid*8 + j]
    float w1r[FFN][8];
    #pragma unroll
    for (int f = 0; f < FFN; ++f) {
        const float4* p4 = reinterpret_cast<const float4*>(W1 + f * EMBED + tid * 8);
        float4 a = p4[0], b = p4[1];
        w1r[f][0] = a.x; w1r[f][1] = a.y; w1r[f][2] = a.z; w1r[f][3] = a.w;
        w1r[f][4] = b.x; w1r[f][5] = b.y; w1r[f][6] = b.z; w1r[f][7] = b.w;
    }
    __syncthreads();

    const int stride = gridDim.x;
    int t = blockIdx.x;

    // Preload first token's x slice.
    float xc[8];
    if (t < ntok) {
        const float4* p4 = reinterpret_cast<const float4*>(x + (size_t)t * EMBED + tid * 8);
        float4 a = p4[0], b = p4[1];
        xc[0] = a.x; xc[1] = a.y; xc[2] = a.z; xc[3] = a.w;
        xc[4] = b.x; xc[5] = b.y; xc[6] = b.z; xc[7] = b.w;
    }

    for (; t < ntok; t += stride) {
        const int tn = t + stride;

        // Prefetch next token (LDG issues early; latency overlaps FMA+reduce+sync).
        float4 a4, b4;
        if (tn < ntok) {
            const float4* p4 = reinterpret_cast<const float4*>(x + (size_t)tn * EMBED + tid * 8);
            a4 = p4[0]; b4 = p4[1];
        }

        // Partial dot products for all 8 filters.
        float acc[FFN];
        #pragma unroll
        for (int f = 0; f < FFN; ++f) acc[f] = 0.0f;
        #pragma unroll
        for (int j = 0; j < 8; ++j) {
            #pragma unroll
            for (int f = 0; f < FFN; ++f)
                acc[f] = fmaf(xc[j], w1r[f][j], acc[f]);
        }

        // Warp butterfly reduce (all lanes end with warp sum).
        #pragma unroll
        for (int off = 16; off > 0; off >>= 1) {
            #pragma unroll
            for (int f = 0; f < FFN; ++f)
                acc[f] += __shfl_xor_sync(0xffffffffu, acc[f], off);
        }
        if ((tid & 31) == 0) {
            const int w = tid >> 5;
            #pragma unroll
            for (int f = 0; f < FFN; ++f) s_part[w][f] = acc[f];
        }
        __syncthreads();

        // Finalize: 8 threads, one filter each.
        if (tid < FFN) {
            float s = s_b1[tid];
            #pragma unroll
            for (int w = 0; w < 8; ++w) s += s_part[w][tid];
            s = fmaxf(s, 0.0f);
            float c = __cosf(s);           // h in [0, ~3]: fast path is accurate
            g_q[(size_t)t * FFN + tid] = c * c;
        }
        __syncthreads();   // protects s_part against next iteration's writes

        if (tn < ntok) {
            xc[0] = a4.x; xc[1] = a4.y; xc[2] = a4.z; xc[3] = a4.w;
            xc[4] = b4.x; xc[5] = b4.y; xc[6] = b4.z; xc[7] = b4.w;
        }
    }
}

// ---------------------------------------------------------------------------
// Kernel 2: out[n,e] = b2[e] + sum_f q[n,f] * W2[e,f]
// No block syncs. W2 slice + b2 in regs (72 regs/thread). q row = 32 B,
// L1-broadcast across the block. 2x STG.128 per thread per token.
// ---------------------------------------------------------------------------
__global__ __launch_bounds__(256, 2)
void qff_gemm2(const float* __restrict__ W2,
               const float* __restrict__ b2,
               float* __restrict__ out,
               int ntok)
{
    const int tid = threadIdx.x;

    // w2r[j][f] = W2[tid*8 + j, f]  (W2 row is 8 contiguous floats)
    float w2r[8][FFN];
    float b2r[8];
    #pragma unroll
    for (int j = 0; j < 8; ++j) {
        const int e = tid * 8 + j;
        const float4* p4 = reinterpret_cast<const float4*>(W2 + e * FFN);
        float4 a = p4[0], b = p4[1];
        w2r[j][0] = a.x; w2r[j][1] = a.y; w2r[j][2] = a.z; w2r[j][3] = a.w;
        w2r[j][4] = b.x; w2r[j][5] = b.y; w2r[j][6] = b.z; w2r[j][7] = b.w;
        b2r[j] = b2[e];
    }

    const int stride = gridDim.x;
    for (int t = blockIdx.x; t < ntok; t += stride) {
        const float4* q4 = reinterpret_cast<const float4*>(g_q + (size_t)t * FFN);
        float4 qa = q4[0], qb = q4[1];
        float qv[FFN];
        qv[0] = qa.x; qv[1] = qa.y; qv[2] = qa.z; qv[3] = qa.w;
        qv[4] = qb.x; qv[5] = qb.y; qv[6] = qb.z; qv[7] = qb.w;

        float o[8];
        #pragma unroll
        for (int j = 0; j < 8; ++j) {
            float v = b2r[j];
            #pragma unroll
            for (int f = 0; f < FFN; ++f)
                v = fmaf(qv[f], w2r[j][f], v);
            o[j] = v;
        }

        float4* o4 = reinterpret_cast<float4*>(out + (size_t)t * EMBED + tid * 8);
        o4[0] = make_float4(o[0], o[1], o[2], o[3]);
        o4[1] = make_float4(o[4], o[5], o[6], o[7]);
    }
}

// ---------------------------------------------------------------------------
// Launch: inputs in metadata order: x, W1, b1, W2, b2. Output float [N, EMBED].
// ---------------------------------------------------------------------------
extern "C" void kernel_launch(void* const* d_in, const int* in_sizes, int n_in,
                              void* d_out, int out_size)
{
    const float* x  = (const float*)d_in[0];
    const float* W1 = (const float*)d_in[1];
    const float* b1 = (const float*)d_in[2];
    const float* W2 = (const float*)d_in[3];
    const float* b2 = (const float*)d_in[4];
    float* out = (float*)d_out;

    int ntok = in_sizes[0] / EMBED;
    if (ntok > MAXTOK) ntok = MAXTOK;

    int dev = 0;
    cudaGetDevice(&dev);
    int sms = 148;
    cudaDeviceGetAttribute(&sms, cudaDevAttrMultiProcessorCount, dev);

    const int grid = sms * 2;   // matches __launch_bounds__(256, 2): one full wave

    qff_gemm1<<<grid, 256>>>(x, W1, b1, ntok);
    qff_gemm2<<<grid, 256>>>(W2, b2, out, ntok);
}

// round 5
// speedup vs baseline: 1.1745x; 1.1745x over previous
#include <cuda_runtime.h>
#include <cuda_bf16.h>

#define EMBED 2048
#define FFN   8
#define MAXTOK 65536

// Intermediate q[N, FFN] scratch (2 MB). Static __device__ array: allocation-free.
__device__ float g_q[MAXTOK * FFN];

// ---- packed f32x2 helpers (FFMA2 only reachable via PTX on sm_103a) ----
__device__ __forceinline__ unsigned long long fma2(unsigned long long a,
                                                   unsigned long long b,
                                                   unsigned long long c) {
    unsigned long long d;
    asm("fma.rn.f32x2 %0, %1, %2, %3;" : "=l"(d) : "l"(a), "l"(b), "l"(c));
    return d;
}
__device__ __forceinline__ unsigned long long pack2(float lo, float hi) {
    unsigned long long d;
    asm("mov.b64 %0, {%1, %2};" : "=l"(d) : "f"(lo), "f"(hi));
    return d;
}
__device__ __forceinline__ void unpack2(unsigned long long v, float& lo, float& hi) {
    asm("mov.b64 {%0, %1}, %2;" : "=f"(lo), "=f"(hi) : "l"(v));
}

// ---------------------------------------------------------------------------
// Kernel 1: q[n,f] = cos^2( relu( x[n,:] . W1[f,:] + b1[f] ) )
// 256 thr/block, thread owns 8 contiguous embed elems (as 4 f32x2 pairs).
// W1 slice register-resident (32 b64). 32 FFMA2 per token per thread.
// Reduction: 9-shuffle transpose-reduce (vs 40 before) + double-buffered
// smem partials (one __syncthreads per token).
// ---------------------------------------------------------------------------
__global__ __launch_bounds__(256, 2)
void qff_gemm1(const float* __restrict__ x,
               const float* __restrict__ W1,
               const float* __restrict__ b1,
               int ntok)
{
    __shared__ float s_part[2][8][FFN];   // [parity][warp][feature]

    const int tid  = threadIdx.x;
    const int lane = tid & 31;
    const int warp = tid >> 5;

    float b1v = 0.0f;
    if (tid < FFN) b1v = b1[tid];

    // Register W1 slice: w1p[f][j] packs W1[f, tid*8+2j], W1[f, tid*8+2j+1]
    unsigned long long w1p[FFN][4];
    #pragma unroll
    for (int f = 0; f < FFN; ++f) {
        const ulonglong2* p = reinterpret_cast<const ulonglong2*>(W1 + f * EMBED + tid * 8);
        ulonglong2 a = p[0], b = p[1];
        w1p[f][0] = a.x; w1p[f][1] = a.y; w1p[f][2] = b.x; w1p[f][3] = b.y;
    }

    const int stride = gridDim.x;
    int t = blockIdx.x;

    // Preload first token's x slice (4 packed pairs).
    unsigned long long xc[4];
    if (t < ntok) {
        const ulonglong2* p = reinterpret_cast<const ulonglong2*>(x + (size_t)t * EMBED + tid * 8);
        ulonglong2 a = p[0], b = p[1];
        xc[0] = a.x; xc[1] = a.y; xc[2] = b.x; xc[3] = b.y;
    }

    int parity = 0;
    for (; t < ntok; t += stride, parity ^= 1) {
        const int tn = t + stride;

        // Prefetch next token early (latency overlaps FMA + reduce).
        ulonglong2 pfa, pfb;
        if (tn < ntok) {
            const ulonglong2* p = reinterpret_cast<const ulonglong2*>(x + (size_t)tn * EMBED + tid * 8);
            pfa = p[0]; pfb = p[1];
        }

        // Packed partial dot products: acc2[f] accumulates elem pairs.
        unsigned long long acc2[FFN];
        #pragma unroll
        for (int f = 0; f < FFN; ++f) acc2[f] = 0ull;
        #pragma unroll
        for (int j = 0; j < 4; ++j) {
            #pragma unroll
            for (int f = 0; f < FFN; ++f)
                acc2[f] = fma2(xc[j], w1p[f][j], acc2[f]);
        }
        float acc[FFN];
        #pragma unroll
        for (int f = 0; f < FFN; ++f) {
            float lo, hi; unpack2(acc2[f], lo, hi);
            acc[f] = lo + hi;
        }

        // 9-shuffle transpose-reduce.
        // Step 1 (xor 1): fold feature bit2. 4 shuffles.
        float v4[4];
        {
            const bool hi = lane & 1;
            #pragma unroll
            for (int k = 0; k < 4; ++k) {
                float keep = hi ? acc[k + 4] : acc[k];
                float send = hi ? acc[k]     : acc[k + 4];
                v4[k] = keep + __shfl_xor_sync(0xffffffffu, send, 1);
            }
        }
        // Step 2 (xor 2): fold feature bit1. 2 shuffles.
        float v2[2];
        {
            const bool hi = lane & 2;
            #pragma unroll
            for (int k = 0; k < 2; ++k) {
                float keep = hi ? v4[k + 2] : v4[k];
                float send = hi ? v4[k]     : v4[k + 2];
                v2[k] = keep + __shfl_xor_sync(0xffffffffu, send, 2);
            }
        }
        // Step 3 (xor 4): fold feature bit0. 1 shuffle.
        float v;
        {
            const bool hi = lane & 4;
            float keep = hi ? v2[1] : v2[0];
            float send = hi ? v2[0] : v2[1];
            v = keep + __shfl_xor_sync(0xffffffffu, send, 4);
        }
        // Steps 4,5: finish warp sum. 2 shuffles.
        v += __shfl_xor_sync(0xffffffffu, v, 8);
        v += __shfl_xor_sync(0xffffffffu, v, 16);
        // lane l holds feature f = ((l&1)<<2) | (l&2) | ((l>>2)&1)

        if (lane < 8) {
            const int f = ((lane & 1) << 2) | (lane & 2) | ((lane >> 2) & 1);
            s_part[parity][warp][f] = v;
        }
        __syncthreads();

        if (tid < FFN) {
            float s = b1v;
            #pragma unroll
            for (int w = 0; w < 8; ++w) s += s_part[parity][w][tid];
            s = fmaxf(s, 0.0f);
            float c = __cosf(s);
            g_q[(size_t)t * FFN + tid] = c * c;
        }
        // No trailing sync: next iteration writes the other parity buffer.

        if (tn < ntok) {
            xc[0] = pfa.x; xc[1] = pfa.y; xc[2] = pfb.x; xc[3] = pfb.y;
        }
    }
}

// ---------------------------------------------------------------------------
// Kernel 2: out[n,e] = b2[e] + sum_f q[n,f] * W2[e,f]
// 256 thr/block, thread owns 8 embed elems. W2 + b2 in regs (packed pairs).
// 4 tokens per iteration: all 8 q-row LDG.128 issued up front (MLP=8),
// then 32 FFMA2 + 2 STG.128 per token.
// ---------------------------------------------------------------------------
__global__ __launch_bounds__(256, 2)
void qff_gemm2(const float* __restrict__ W2,
               const float* __restrict__ b2,
               float* __restrict__ out,
               int ntok)
{
    const int tid = threadIdx.x;

    // w2p[p][f] packs (W2[e2p, f], W2[e2p+1, f]) for e2p = tid*8 + 2p.
    unsigned long long w2p[4][FFN];
    unsigned long long b2p[4];
    #pragma unroll
    for (int p = 0; p < 4; ++p) {
        const int e0 = tid * 8 + 2 * p;
        const float4* r0 = reinterpret_cast<const float4*>(W2 + (size_t)e0 * FFN);
        const float4* r1 = reinterpret_cast<const float4*>(W2 + (size_t)(e0 + 1) * FFN);
        float4 a0 = r0[0], a1 = r0[1];
        float4 c0 = r1[0], c1 = r1[1];
        w2p[p][0] = pack2(a0.x, c0.x); w2p[p][1] = pack2(a0.y, c0.y);
        w2p[p][2] = pack2(a0.z, c0.z); w2p[p][3] = pack2(a0.w, c0.w);
        w2p[p][4] = pack2(a1.x, c1.x); w2p[p][5] = pack2(a1.y, c1.y);
        w2p[p][6] = pack2(a1.z, c1.z); w2p[p][7] = pack2(a1.w, c1.w);
        b2p[p] = pack2(b2[e0], b2[e0 + 1]);
    }

    const int step = gridDim.x * 4;
    for (int t = blockIdx.x * 4; t < ntok; t += step) {
        // Issue all q loads for up to 4 tokens first (MLP=8).
        ulonglong2 qv[4][2];
        #pragma unroll
        for (int k = 0; k < 4; ++k) {
            if (t + k < ntok) {
                const ulonglong2* p = reinterpret_cast<const ulonglong2*>(g_q + (size_t)(t + k) * FFN);
                qv[k][0] = p[0]; qv[k][1] = p[1];
            }
        }

        #pragma unroll
        for (int k = 0; k < 4; ++k) {
            if (t + k >= ntok) break;
            float qf[FFN];
            unpack2(qv[k][0].x, qf[0], qf[1]);
            unpack2(qv[k][0].y, qf[2], qf[3]);
            unpack2(qv[k][1].x, qf[4], qf[5]);
            unpack2(qv[k][1].y, qf[6], qf[7]);

            unsigned long long o2[4];
            #pragma unroll
            for (int p = 0; p < 4; ++p) o2[p] = b2p[p];
            #pragma unroll
            for (int f = 0; f < FFN; ++f) {
                const unsigned long long qd = pack2(qf[f], qf[f]);
                #pragma unroll
                for (int p = 0; p < 4; ++p)
                    o2[p] = fma2(w2p[p][f], qd, o2[p]);
            }

            ulonglong2* o4 = reinterpret_cast<ulonglong2*>(out + (size_t)(t + k) * EMBED + tid * 8);
            ulonglong2 s0; s0.x = o2[0]; s0.y = o2[1];
            ulonglong2 s1; s1.x = o2[2]; s1.y = o2[3];
            o4[0] = s0;
            o4[1] = s1;
        }
    }
}

// ---------------------------------------------------------------------------
// Launch: inputs in metadata order: x, W1, b1, W2, b2. Output float [N, EMBED].
// ---------------------------------------------------------------------------
extern "C" void kernel_launch(void* const* d_in, const int* in_sizes, int n_in,
                              void* d_out, int out_size)
{
    const float* x  = (const float*)d_in[0];
    const float* W1 = (const float*)d_in[1];
    const float* b1 = (const float*)d_in[2];
    const float* W2 = (const float*)d_in[3];
    const float* b2 = (const float*)d_in[4];
    float* out = (float*)d_out;

    int ntok = in_sizes[0] / EMBED;
    if (ntok > MAXTOK) ntok = MAXTOK;

    int dev = 0;
    cudaGetDevice(&dev);
    int sms = 148;
    cudaDeviceGetAttribute(&sms, cudaDevAttrMultiProcessorCount, dev);

    const int grid = sms * 2;   // one full wave at 2 blocks/SM

    qff_gemm1<<<grid, 256>>>(x, W1, b1, ntok);
    qff_gemm2<<<grid, 256>>>(W2, b2, out, ntok);
}

// round 6
// speedup vs baseline: 1.2276x; 1.0452x over previous
#include <cuda_runtime.h>
#include <cuda_bf16.h>

#define EMBED 2048
#define FFN   8
#define G     4          // tokens per stage

// ---- packed f32x2 helpers (FFMA2 only reachable via PTX on sm_103a) ----
__device__ __forceinline__ unsigned long long fma2(unsigned long long a,
                                                   unsigned long long b,
                                                   unsigned long long c) {
    unsigned long long d;
    asm("fma.rn.f32x2 %0, %1, %2, %3;" : "=l"(d) : "l"(a), "l"(b), "l"(c));
    return d;
}
__device__ __forceinline__ unsigned long long pack2(float lo, float hi) {
    unsigned long long d;
    asm("mov.b64 %0, {%1, %2};" : "=l"(d) : "f"(lo), "f"(hi));
    return d;
}
__device__ __forceinline__ void unpack2(unsigned long long v, float& lo, float& hi) {
    asm("mov.b64 {%0, %1}, %2;" : "=f"(lo), "=f"(hi) : "l"(v));
}

// ---------------------------------------------------------------------------
// Fused kernel: out[n,:] = W2 @ cos^2(relu(W1 @ x[n,:] + b1)) + b2
// One block per SM, 256 threads, thread owns 8 contiguous embed cols for both
// GEMMs (W1: 64 regs, W2: 64 regs, register-resident). Stages of G=4 tokens:
//   A: 128 FFMA2 partials -> prefetch next stage x into same regs -> shuffles
//   bar -> finalize (G*8 threads: 8 adds + cosf^2 -> smem q) -> bar
//   B: per token 32 FFMA2 + 2x STG.128
// Read (x) and write (out) HBM streams overlap inside one kernel.
// ---------------------------------------------------------------------------
__global__ __launch_bounds__(256, 1)
void qff_fused(const float* __restrict__ x,
               const float* __restrict__ W1,
               const float* __restrict__ b1,
               const float* __restrict__ W2,
               const float* __restrict__ b2,
               float* __restrict__ out,
               int ntok)
{
    __shared__ float s_part[G][8][FFN];  // [token][warp][feature]
    __shared__ float s_q[G][FFN];
    __shared__ float s_b1[FFN];

    const int tid  = threadIdx.x;
    const int lane = tid & 31;
    const int warp = tid >> 5;

    if (tid < FFN) s_b1[tid] = b1[tid];

    // ---- register-resident weights ----
    // w1p[f][j] packs W1[f, tid*8+2j .. +2j+1]
    unsigned long long w1p[FFN][4];
    #pragma unroll
    for (int f = 0; f < FFN; ++f) {
        const ulonglong2* p = reinterpret_cast<const ulonglong2*>(W1 + f * EMBED + tid * 8);
        ulonglong2 a = p[0], b = p[1];
        w1p[f][0] = a.x; w1p[f][1] = a.y; w1p[f][2] = b.x; w1p[f][3] = b.y;
    }
    // w2p[p][f] packs (W2[e,f], W2[e+1,f]) for e = tid*8 + 2p
    unsigned long long w2p[4][FFN];
    unsigned long long b2p[4];
    #pragma unroll
    for (int p = 0; p < 4; ++p) {
        const int e0 = tid * 8 + 2 * p;
        const float4* r0 = reinterpret_cast<const float4*>(W2 + (size_t)e0 * FFN);
        const float4* r1 = reinterpret_cast<const float4*>(W2 + (size_t)(e0 + 1) * FFN);
        float4 a0 = r0[0], a1 = r0[1];
        float4 c0 = r1[0], c1 = r1[1];
        w2p[p][0] = pack2(a0.x, c0.x); w2p[p][1] = pack2(a0.y, c0.y);
        w2p[p][2] = pack2(a0.z, c0.z); w2p[p][3] = pack2(a0.w, c0.w);
        w2p[p][4] = pack2(a1.x, c1.x); w2p[p][5] = pack2(a1.y, c1.y);
        w2p[p][6] = pack2(a1.z, c1.z); w2p[p][7] = pack2(a1.w, c1.w);
        b2p[p] = pack2(b2[e0], b2[e0 + 1]);
    }
    __syncthreads();

    const int stageStride = gridDim.x * G;   // tokens per full grid step
    int t0 = blockIdx.x * G;

    // ---- preload first stage's x slices ----
    unsigned long long xg[G][4];
    #pragma unroll
    for (int g = 0; g < G; ++g) {
        if (t0 + g < ntok) {
            const ulonglong2* p = reinterpret_cast<const ulonglong2*>(
                x + (size_t)(t0 + g) * EMBED + tid * 8);
            ulonglong2 a = p[0], b = p[1];
            xg[g][0] = a.x; xg[g][1] = a.y; xg[g][2] = b.x; xg[g][3] = b.y;
        }
    }

    for (; t0 < ntok; t0 += stageStride) {
        const int tn0 = t0 + stageStride;

        // ---------- Phase A: partial dot products for G tokens ----------
        float acc[G][FFN];
        #pragma unroll
        for (int g = 0; g < G; ++g) {
            unsigned long long a2[FFN];
            #pragma unroll
            for (int f = 0; f < FFN; ++f) a2[f] = 0ull;
            #pragma unroll
            for (int j = 0; j < 4; ++j) {
                #pragma unroll
                for (int f = 0; f < FFN; ++f)
                    a2[f] = fma2(xg[g][j], w1p[f][j], a2[f]);
            }
            #pragma unroll
            for (int f = 0; f < FFN; ++f) {
                float lo, hi; unpack2(a2[f], lo, hi);
                acc[g][f] = lo + hi;
            }
        }

        // ---------- Prefetch next stage into xg (regs now dead) ----------
        // Load->use distance: shuffles + 2 bars + finalize + phase B (~600 cyc).
        #pragma unroll
        for (int g = 0; g < G; ++g) {
            if (tn0 + g < ntok) {
                const ulonglong2* p = reinterpret_cast<const ulonglong2*>(
                    x + (size_t)(tn0 + g) * EMBED + tid * 8);
                ulonglong2 a = p[0], b = p[1];
                xg[g][0] = a.x; xg[g][1] = a.y; xg[g][2] = b.x; xg[g][3] = b.y;
            }
        }

        // ---------- 9-shuffle transpose-reduce per token (overlapped) ----------
        #pragma unroll
        for (int g = 0; g < G; ++g) {
            float v4[4];
            {
                const bool hi = lane & 1;
                #pragma unroll
                for (int k = 0; k < 4; ++k) {
                    float keep = hi ? acc[g][k + 4] : acc[g][k];
                    float send = hi ? acc[g][k]     : acc[g][k + 4];
                    v4[k] = keep + __shfl_xor_sync(0xffffffffu, send, 1);
                }
            }
            float v2[2];
            {
                const bool hi = lane & 2;
                #pragma unroll
                for (int k = 0; k < 2; ++k) {
                    float keep = hi ? v4[k + 2] : v4[k];
                    float send = hi ? v4[k]     : v4[k + 2];
                    v2[k] = keep + __shfl_xor_sync(0xffffffffu, send, 2);
                }
            }
            float v;
            {
                const bool hi = lane & 4;
                float keep = hi ? v2[1] : v2[0];
                float send = hi ? v2[0] : v2[1];
                v = keep + __shfl_xor_sync(0xffffffffu, send, 4);
            }
            v += __shfl_xor_sync(0xffffffffu, v, 8);
            v += __shfl_xor_sync(0xffffffffu, v, 16);
            // lane l holds feature f = ((l&1)<<2) | (l&2) | ((l>>2)&1)
            if (lane < 8) {
                const int f = ((lane & 1) << 2) | (lane & 2) | ((lane >> 2) & 1);
                s_part[g][warp][f] = v;
            }
        }
        __syncthreads();

        // ---------- Finalize: G*8 threads, one (token, feature) each ----------
        if (tid < G * FFN) {
            const int g = tid >> 3;
            const int f = tid & 7;
            if (t0 + g < ntok) {
                float s = s_b1[f];
                #pragma unroll
                for (int w = 0; w < 8; ++w) s += s_part[g][w][f];
                s = fmaxf(s, 0.0f);
                float c = __cosf(s);
                s_q[g][f] = c * c;
            }
        }
        __syncthreads();

        // ---------- Phase B: out rows for G tokens ----------
        #pragma unroll
        for (int g = 0; g < G; ++g) {
            const int t = t0 + g;
            if (t >= ntok) break;
            float qf[FFN];
            #pragma unroll
            for (int f = 0; f < FFN; ++f) qf[f] = s_q[g][f];

            unsigned long long o2[4];
            #pragma unroll
            for (int p = 0; p < 4; ++p) o2[p] = b2p[p];
            #pragma unroll
            for (int f = 0; f < FFN; ++f) {
                const unsigned long long qd = pack2(qf[f], qf[f]);
                #pragma unroll
                for (int p = 0; p < 4; ++p)
                    o2[p] = fma2(w2p[p][f], qd, o2[p]);
            }

            ulonglong2* o4 = reinterpret_cast<ulonglong2*>(
                out + (size_t)t * EMBED + tid * 8);
            ulonglong2 s0; s0.x = o2[0]; s0.y = o2[1];
            ulonglong2 s1; s1.x = o2[2]; s1.y = o2[3];
            o4[0] = s0;
            o4[1] = s1;
        }
        // No trailing bar: next stage's s_part/s_q writes are separated from
        // this stage's reads by the two bars inside the next iteration.
    }
}

// ---------------------------------------------------------------------------
// Launch: inputs in metadata order: x, W1, b1, W2, b2. Output float [N, EMBED].
// ---------------------------------------------------------------------------
extern "C" void kernel_launch(void* const* d_in, const int* in_sizes, int n_in,
                              void* d_out, int out_size)
{
    const float* x  = (const float*)d_in[0];
    const float* W1 = (const float*)d_in[1];
    const float* b1 = (const float*)d_in[2];
    const float* W2 = (const float*)d_in[3];
    const float* b2 = (const float*)d_in[4];
    float* out = (float*)d_out;

    int ntok = in_sizes[0] / EMBED;

    int dev = 0;
    cudaGetDevice(&dev);
    int sms = 148;
    cudaDeviceGetAttribute(&sms, cudaDevAttrMultiProcessorCount, dev);

    qff_fused<<<sms, 256>>>(x, W1, b1, W2, b2, out, ntok);
}

// round 7
// speedup vs baseline: 1.3627x; 1.1100x over previous
#include <cuda_runtime.h>
#include <cuda_bf16.h>

#define EMBED 2048
#define FFN   8
#define MAXTOK 65536
#define CHUNK 16            // tokens per handoff flag
#define GP    4             // producer stage tokens
#define GC    2             // consumer stage tokens
#define MAXPAIR 256
#define MAXCHUNKS 64

// q[N, FFN] handoff buffer (2 MB, L2-resident) + per-(pair,chunk) ready flags.
__device__ float g_q[MAXTOK * FFN];
__device__ int   g_flags[MAXPAIR * MAXCHUNKS];

// ---- packed f32x2 helpers ----
__device__ __forceinline__ unsigned long long fma2(unsigned long long a,
                                                   unsigned long long b,
                                                   unsigned long long c) {
    unsigned long long d;
    asm("fma.rn.f32x2 %0, %1, %2, %3;" : "=l"(d) : "l"(a), "l"(b), "l"(c));
    return d;
}
__device__ __forceinline__ unsigned long long pack2(float lo, float hi) {
    unsigned long long d;
    asm("mov.b64 %0, {%1, %2};" : "=l"(d) : "f"(lo), "f"(hi));
    return d;
}
__device__ __forceinline__ void unpack2(unsigned long long v, float& lo, float& hi) {
    asm("mov.b64 {%0, %1}, %2;" : "=f"(lo), "=f"(hi) : "l"(v));
}

// ---------------------------------------------------------------------------
// Flag reset (runs before the main kernel each launch; graph-capturable).
// ---------------------------------------------------------------------------
__global__ void qff_reset(int n)
{
    for (int i = blockIdx.x * blockDim.x + threadIdx.x; i < n;
         i += gridDim.x * blockDim.x)
        g_flags[i] = 0;
}

// ---------------------------------------------------------------------------
// Producer/consumer kernel. grid = 2*npairs, 2 blocks co-resident per SM:
//   blocks [0, npairs):        producer — gemm1 + cos^2 -> g_q, sets flags
//   blocks [npairs, 2*npairs): consumer — g_q -> gemm2 -> out, polls flags
// Pair i handles tokens [i*tpb, min((i+1)*tpb, ntok)).
// ---------------------------------------------------------------------------
__global__ __launch_bounds__(256, 2)
void qff_pc(const float* __restrict__ x,
            const float* __restrict__ W1,
            const float* __restrict__ b1,
            const float* __restrict__ W2,
            const float* __restrict__ b2,
            float* __restrict__ out,
            int ntok, int npairs, int tpb)
{
    const int tid  = threadIdx.x;
    const int lane = tid & 31;
    const int warp = tid >> 5;

    if (blockIdx.x < (unsigned)npairs) {
        // ==================== PRODUCER ====================
        const int pair  = blockIdx.x;
        const int start = pair * tpb;
        const int end   = min(start + tpb, ntok);
        if (start >= end) return;

        __shared__ float s_part[2][GP][8][FFN];   // [parity][token][warp][f]
        __shared__ float s_b1[FFN];
        if (tid < FFN) s_b1[tid] = b1[tid];

        // W1 slice register-resident: w1p[f][j] packs cols tid*8+2j, +2j+1
        unsigned long long w1p[FFN][4];
        #pragma unroll
        for (int f = 0; f < FFN; ++f) {
            const ulonglong2* p = reinterpret_cast<const ulonglong2*>(W1 + f * EMBED + tid * 8);
            ulonglong2 a = p[0], b = p[1];
            w1p[f][0] = a.x; w1p[f][1] = a.y; w1p[f][2] = b.x; w1p[f][3] = b.y;
        }

        // Preload first stage x.
        unsigned long long xg[GP][4];
        #pragma unroll
        for (int g = 0; g < GP; ++g) {
            if (start + g < end) {
                const ulonglong2* p = reinterpret_cast<const ulonglong2*>(
                    x + (size_t)(start + g) * EMBED + tid * 8);
                ulonglong2 a = p[0], b = p[1];
                xg[g][0] = a.x; xg[g][1] = a.y; xg[g][2] = b.x; xg[g][3] = b.y;
            }
        }

        int parity = 0;
        volatile int* flags = g_flags + pair * MAXCHUNKS;

        for (int t0 = start; t0 < end; t0 += GP, parity ^= 1) {
            // Partials + first 3 shuffle rounds per token (acc short-lived).
            float vstage[GP];
            #pragma unroll
            for (int g = 0; g < GP; ++g) {
                unsigned long long a2[FFN];
                #pragma unroll
                for (int f = 0; f < FFN; ++f) a2[f] = 0ull;
                #pragma unroll
                for (int j = 0; j < 4; ++j) {
                    #pragma unroll
                    for (int f = 0; f < FFN; ++f)
                        a2[f] = fma2(xg[g][j], w1p[f][j], a2[f]);
                }
                float acc[FFN];
                #pragma unroll
                for (int f = 0; f < FFN; ++f) {
                    float lo, hi; unpack2(a2[f], lo, hi);
                    acc[f] = lo + hi;
                }
                float v4[4];
                {
                    const bool hi = lane & 1;
                    #pragma unroll
                    for (int k = 0; k < 4; ++k) {
                        float keep = hi ? acc[k + 4] : acc[k];
                        float send = hi ? acc[k]     : acc[k + 4];
                        v4[k] = keep + __shfl_xor_sync(0xffffffffu, send, 1);
                    }
                }
                float v2[2];
                {
                    const bool hi = lane & 2;
                    #pragma unroll
                    for (int k = 0; k < 2; ++k) {
                        float keep = hi ? v4[k + 2] : v4[k];
                        float send = hi ? v4[k]     : v4[k + 2];
                        v2[k] = keep + __shfl_xor_sync(0xffffffffu, send, 2);
                    }
                }
                {
                    const bool hi = lane & 4;
                    float keep = hi ? v2[1] : v2[0];
                    float send = hi ? v2[0] : v2[1];
                    vstage[g] = keep + __shfl_xor_sync(0xffffffffu, send, 4);
                }
            }

            // Prefetch next stage into xg (dead now; use distance ~1 stage).
            const int tn0 = t0 + GP;
            #pragma unroll
            for (int g = 0; g < GP; ++g) {
                if (tn0 + g < end) {
                    const ulonglong2* p = reinterpret_cast<const ulonglong2*>(
                        x + (size_t)(tn0 + g) * EMBED + tid * 8);
                    ulonglong2 a = p[0], b = p[1];
                    xg[g][0] = a.x; xg[g][1] = a.y; xg[g][2] = b.x; xg[g][3] = b.y;
                }
            }

            // Finish warp reduction, stash per-warp partials.
            #pragma unroll
            for (int g = 0; g < GP; ++g) {
                float v = vstage[g];
                v += __shfl_xor_sync(0xffffffffu, v, 8);
                v += __shfl_xor_sync(0xffffffffu, v, 16);
                if (lane < 8) {
                    const int f = ((lane & 1) << 2) | (lane & 2) | ((lane >> 2) & 1);
                    s_part[parity][g][warp][f] = v;
                }
            }
            __syncthreads();

            // Finalize (GP*8 threads): cross-warp sum + cos^2 -> g_q.
            if (tid < GP * FFN) {
                const int g = tid >> 3;
                const int f = tid & 7;
                const int t = t0 + g;
                if (t < end) {
                    float s = s_b1[f];
                    #pragma unroll
                    for (int w = 0; w < 8; ++w) s += s_part[parity][g][w][f];
                    s = fmaxf(s, 0.0f);
                    float c = __cosf(s);
                    g_q[(size_t)t * FFN + f] = c * c;
                }
            }

            // Chunk boundary: publish flag (store -> fence -> bar -> flag).
            const int done = min(t0 + GP, end) - start;
            if ((done & (CHUNK - 1)) == 0 || t0 + GP >= end) {
                __threadfence();
                __syncthreads();
                if (tid == 0) flags[(done - 1) >> 4] = 1;
            }
            // Parity double-buffer: no trailing bar otherwise (next stage's
            // STS targets the other buffer; the stage-after is separated by
            // the intervening __syncthreads()).
        }
    } else {
        // ==================== CONSUMER ====================
        const int pair  = blockIdx.x - npairs;
        const int start = pair * tpb;
        const int end   = min(start + tpb, ntok);
        if (start >= end) return;

        // W2 slice + b2 register-resident (packed pairs).
        unsigned long long w2p[4][FFN];
        unsigned long long b2p[4];
        #pragma unroll
        for (int p = 0; p < 4; ++p) {
            const int e0 = tid * 8 + 2 * p;
            const float4* r0 = reinterpret_cast<const float4*>(W2 + (size_t)e0 * FFN);
            const float4* r1 = reinterpret_cast<const float4*>(W2 + (size_t)(e0 + 1) * FFN);
            float4 a0 = r0[0], a1 = r0[1];
            float4 c0 = r1[0], c1 = r1[1];
            w2p[p][0] = pack2(a0.x, c0.x); w2p[p][1] = pack2(a0.y, c0.y);
            w2p[p][2] = pack2(a0.z, c0.z); w2p[p][3] = pack2(a0.w, c0.w);
            w2p[p][4] = pack2(a1.x, c1.x); w2p[p][5] = pack2(a1.y, c1.y);
            w2p[p][6] = pack2(a1.z, c1.z); w2p[p][7] = pack2(a1.w, c1.w);
            b2p[p] = pack2(b2[e0], b2[e0 + 1]);
        }

        volatile int* flags = g_flags + pair * MAXCHUNKS;
        const int nchunks = (end - start + CHUNK - 1) / CHUNK;

        for (int c = 0; c < nchunks; ++c) {
            if (tid == 0) {
                while (flags[c] == 0) __nanosleep(64);
                __threadfence();
            }
            __syncthreads();

            const int cstart = start + c * CHUNK;
            const int cend   = min(cstart + CHUNK, end);

            for (int t0 = cstart; t0 < cend; t0 += GC) {
                // q rows via L2 (__ldcg: coherent with producer stores).
                uint4 qv[GC][2];
                #pragma unroll
                for (int k = 0; k < GC; ++k) {
                    if (t0 + k < cend) {
                        const uint4* qp = reinterpret_cast<const uint4*>(
                            g_q + (size_t)(t0 + k) * FFN);
                        qv[k][0] = __ldcg(qp);
                        qv[k][1] = __ldcg(qp + 1);
                    }
                }
                #pragma unroll
                for (int k = 0; k < GC; ++k) {
                    const int t = t0 + k;
                    if (t >= cend) break;
                    float qf[FFN];
                    qf[0] = __uint_as_float(qv[k][0].x);
                    qf[1] = __uint_as_float(qv[k][0].y);
                    qf[2] = __uint_as_float(qv[k][0].z);
                    qf[3] = __uint_as_float(qv[k][0].w);
                    qf[4] = __uint_as_float(qv[k][1].x);
                    qf[5] = __uint_as_float(qv[k][1].y);
                    qf[6] = __uint_as_float(qv[k][1].z);
                    qf[7] = __uint_as_float(qv[k][1].w);

                    unsigned long long o2[4];
                    #pragma unroll
                    for (int p = 0; p < 4; ++p) o2[p] = b2p[p];
                    #pragma unroll
                    for (int f = 0; f < FFN; ++f) {
                        const unsigned long long qd = pack2(qf[f], qf[f]);
                        #pragma unroll
                        for (int p = 0; p < 4; ++p)
                            o2[p] = fma2(w2p[p][f], qd, o2[p]);
                    }

                    ulonglong2* o4 = reinterpret_cast<ulonglong2*>(
                        out + (size_t)t * EMBED + tid * 8);
                    ulonglong2 s0; s0.x = o2[0]; s0.y = o2[1];
                    ulonglong2 s1; s1.x = o2[2]; s1.y = o2[3];
                    o4[0] = s0;
                    o4[1] = s1;
                }
            }
        }
    }
}

// ---------------------------------------------------------------------------
// Launch: inputs in metadata order: x, W1, b1, W2, b2. Output float [N, EMBED].
// ---------------------------------------------------------------------------
extern "C" void kernel_launch(void* const* d_in, const int* in_sizes, int n_in,
                              void* d_out, int out_size)
{
    const float* x  = (const float*)d_in[0];
    const float* W1 = (const float*)d_in[1];
    const float* b1 = (const float*)d_in[2];
    const float* W2 = (const float*)d_in[3];
    const float* b2 = (const float*)d_in[4];
    float* out = (float*)d_out;

    int ntok = in_sizes[0] / EMBED;
    if (ntok > MAXTOK) ntok = MAXTOK;

    int dev = 0;
    cudaGetDevice(&dev);
    int sms = 148;
    cudaDeviceGetAttribute(&sms, cudaDevAttrMultiProcessorCount, dev);
    int npairs = sms;
    if (npairs > MAXPAIR) npairs = MAXPAIR;

    const int tpb = (ntok + npairs - 1) / npairs;   // tokens per pair (<= 64 chunks)

    qff_reset<<<40, 256>>>(npairs * MAXCHUNKS);
    qff_pc<<<2 * npairs, 256>>>(x, W1, b1, W2, b2, out, ntok, npairs, tpb);
}

// round 9
// speedup vs baseline: 1.7243x; 1.2654x over previous
#include <cuda_runtime.h>
#include <cuda_bf16.h>
#include <cstdint>

#define EMBED  2048
#define FFN    8
#define GP     4        // tokens per stage
#define NSTAGE 4        // ring depth (stages)
#define PDIST  3        // cp.async prefetch distance (stages)

#define BAR_PROD   9
#define BAR_FULL(s)  (1 + (s))   // producer arrives, consumer syncs
#define BAR_EMPTY(s) (5 + (s))   // consumer arrives, producer syncs

// ---- packed f32x2 helpers ----
__device__ __forceinline__ unsigned long long fma2(unsigned long long a,
                                                   unsigned long long b,
                                                   unsigned long long c) {
    unsigned long long d;
    asm("fma.rn.f32x2 %0, %1, %2, %3;" : "=l"(d) : "l"(a), "l"(b), "l"(c));
    return d;
}
__device__ __forceinline__ unsigned long long pack2(float lo, float hi) {
    unsigned long long d;
    asm("mov.b64 %0, {%1, %2};" : "=l"(d) : "f"(lo), "f"(hi));
    return d;
}
__device__ __forceinline__ void unpack2(unsigned long long v, float& lo, float& hi) {
    asm("mov.b64 {%0, %1}, %2;" : "=f"(lo), "=f"(hi) : "l"(v));
}

__device__ __forceinline__ void bar_sync(int id, int cnt) {
    asm volatile("bar.sync %0, %1;" :: "r"(id), "r"(cnt) : "memory");
}
__device__ __forceinline__ void bar_arrive(int id, int cnt) {
    asm volatile("bar.arrive %0, %1;" :: "r"(id), "r"(cnt) : "memory");
}
__device__ __forceinline__ void cp16(uint32_t saddr, const void* gaddr) {
    asm volatile("cp.async.cg.shared.global [%0], [%1], 16;"
                 :: "r"(saddr), "l"(gaddr) : "memory");
}
__device__ __forceinline__ void cp_commit() {
    asm volatile("cp.async.commit_group;" ::: "memory");
}
__device__ __forceinline__ void cp_wait2() {
    asm volatile("cp.async.wait_group 2;" ::: "memory");
}

// smem layout (floats):
//   xring : NSTAGE*GP*EMBED = 32768
//   s_part: GP*8*FFN        = 256
//   s_q   : NSTAGE*GP*FFN   = 128
//   s_b1  : FFN
#define XRING_F  (NSTAGE * GP * EMBED)
#define SPART_F  (GP * 8 * FFN)
#define SQ_F     (NSTAGE * GP * FFN)
#define SMEM_F   (XRING_F + SPART_F + SQ_F + FFN)
#define SMEM_BYTES (SMEM_F * 4)

// ---------------------------------------------------------------------------
// Warp-specialized kernel: 1 block/SM, 512 threads.
//   warps 0-7  (tid 0-255):  producer — x -> gemm1 -> cos^2 -> s_q ring
//   warps 8-15 (tid 256-511): consumer — s_q ring -> gemm2 -> out
// x staged through a 4-stage cp.async smem ring (prefetch 3 stages ahead);
// q handed off through a 4-stage smem ring with named full/empty barriers.
// ---------------------------------------------------------------------------
__global__ __launch_bounds__(512, 1)
void qff_ws(const float* __restrict__ x,
            const float* __restrict__ W1,
            const float* __restrict__ b1,
            const float* __restrict__ W2,
            const float* __restrict__ b2,
            float* __restrict__ out,
            int ntok, int tpb)
{
    extern __shared__ float smem[];
    float* xring  = smem;
    float* s_part = smem + XRING_F;
    float* s_q    = smem + XRING_F + SPART_F;
    float* s_b1   = smem + XRING_F + SPART_F + SQ_F;

    const int tid   = threadIdx.x;
    const int start = blockIdx.x * tpb;
    const int end   = min(start + tpb, ntok);
    if (start >= end) return;                      // uniform for whole block
    const int nst = (end - start + GP - 1) / GP;

    if (tid < 256) {
        // ==================== PRODUCER (warps 0-7) ====================
        const int lane = tid & 31;
        const int warp = tid >> 5;
        if (tid < FFN) s_b1[tid] = b1[tid];

        // W1 slice register-resident: w1p[f][j] packs cols tid*8+2j, +2j+1
        unsigned long long w1p[FFN][4];
        #pragma unroll
        for (int f = 0; f < FFN; ++f) {
            const ulonglong2* p = reinterpret_cast<const ulonglong2*>(
                W1 + f * EMBED + tid * 8);
            ulonglong2 a = p[0], b = p[1];
            w1p[f][0] = a.x; w1p[f][1] = a.y; w1p[f][2] = b.x; w1p[f][3] = b.y;
        }

        // This thread's byte address inside a token row of the ring.
        const uint32_t xr = (uint32_t)__cvta_generic_to_shared(xring) + tid * 32;

        // Prologue: prefetch stages 0..PDIST-1 (one commit group per stage).
        for (int ps = 0; ps < PDIST; ++ps) {
            #pragma unroll
            for (int g = 0; g < GP; ++g) {
                const int t = start + ps * GP + g;
                if (t < end) {
                    const uint32_t dst = xr + (uint32_t)((ps * GP + g) * EMBED) * 4u;
                    const float* src = x + (size_t)t * EMBED + tid * 8;
                    cp16(dst, src);
                    cp16(dst + 16, src + 4);
                }
            }
            cp_commit();
        }

        for (int st = 0; st < nst; ++st) {
            const int s  = st & (NSTAGE - 1);
            const int t0 = start + st * GP;

            cp_wait2();                 // stage st's x ready (per-thread cells)
            bar_sync(BAR_PROD, 256);    // finalize(st-1) done -> s_part reusable

            // Prefetch stage st+PDIST into slot (st+PDIST)%4 (consumed at st-1).
            {
                const int pst  = st + PDIST;
                const int slot = pst & (NSTAGE - 1);
                #pragma unroll
                for (int g = 0; g < GP; ++g) {
                    const int t = start + pst * GP + g;
                    if (t < end) {
                        const uint32_t dst = xr + (uint32_t)((slot * GP + g) * EMBED) * 4u;
                        const float* src = x + (size_t)t * EMBED + tid * 8;
                        cp16(dst, src);
                        cp16(dst + 16, src + 4);
                    }
                }
                cp_commit();            // always commit (keeps wait_group math)
            }

            // Compute GP tokens: LDS x, 32 fma2, fold to vst[g].
            float vst[GP];
            #pragma unroll
            for (int g = 0; g < GP; ++g) {
                const ulonglong2* p = reinterpret_cast<const ulonglong2*>(
                    xring + (s * GP + g) * EMBED + tid * 8);
                ulonglong2 a = p[0], b = p[1];
                unsigned long long xv[4] = {a.x, a.y, b.x, b.y};

                unsigned long long a2[FFN];
                #pragma unroll
                for (int f = 0; f < FFN; ++f) a2[f] = 0ull;
                #pragma unroll
                for (int j = 0; j < 4; ++j) {
                    #pragma unroll
                    for (int f = 0; f < FFN; ++f)
                        a2[f] = fma2(xv[j], w1p[f][j], a2[f]);
                }
                float acc[FFN];
                #pragma unroll
                for (int f = 0; f < FFN; ++f) {
                    float lo, hi; unpack2(a2[f], lo, hi);
                    acc[f] = lo + hi;
                }
                // transpose-reduce rounds xor1, xor2, xor4
                float v4[4];
                {
                    const bool hi = lane & 1;
                    #pragma unroll
                    for (int k = 0; k < 4; ++k) {
                        float keep = hi ? acc[k + 4] : acc[k];
                        float send = hi ? acc[k]     : acc[k + 4];
                        v4[k] = keep + __shfl_xor_sync(0xffffffffu, send, 1);
                    }
                }
                float v2[2];
                {
                    const bool hi = lane & 2;
                    #pragma unroll
                    for (int k = 0; k < 2; ++k) {
                        float keep = hi ? v4[k + 2] : v4[k];
                        float send = hi ? v4[k]     : v4[k + 2];
                        v2[k] = keep + __shfl_xor_sync(0xffffffffu, send, 2);
                    }
                }
                {
                    const bool hi = lane & 4;
                    float keep = hi ? v2[1] : v2[0];
                    float send = hi ? v2[0] : v2[1];
                    vst[g] = keep + __shfl_xor_sync(0xffffffffu, send, 4);
                }
            }

            // Finish warp reduction, stash per-warp partials.
            #pragma unroll
            for (int g = 0; g < GP; ++g) {
                float v = vst[g];
                v += __shfl_xor_sync(0xffffffffu, v, 8);
                v += __shfl_xor_sync(0xffffffffu, v, 16);
                if (lane < 8) {
                    const int f = ((lane & 1) << 2) | (lane & 2) | ((lane >> 2) & 1);
                    s_part[(g * 8 + warp) * FFN + f] = v;
                }
            }

            // q slot s free (consumer arrived) + orders s_part for finalize.
            bar_sync(BAR_EMPTY(s), 512);

            // Finalize: warp g handles token g, lane = feature.
            if (warp < GP && lane < FFN) {
                const int g = warp;
                const int t = t0 + g;
                if (t < end) {
                    float sum = s_b1[lane];
                    #pragma unroll
                    for (int w = 0; w < 8; ++w)
                        sum += s_part[(g * 8 + w) * FFN + lane];
                    sum = fmaxf(sum, 0.0f);
                    float c = __cosf(sum);
                    s_q[(s * GP + g) * FFN + lane] = c * c;
                }
            }
            bar_arrive(BAR_FULL(s), 512);
        }
    } else {
        // ==================== CONSUMER (warps 8-15) ====================
        const int ct = tid - 256;

        // W2 slice + b2 register-resident (packed pairs).
        unsigned long long w2p[4][FFN];
        unsigned long long b2p[4];
        #pragma unroll
        for (int p = 0; p < 4; ++p) {
            const int e0 = ct * 8 + 2 * p;
            const float4* r0 = reinterpret_cast<const float4*>(W2 + (size_t)e0 * FFN);
            const float4* r1 = reinterpret_cast<const float4*>(W2 + (size_t)(e0 + 1) * FFN);
            float4 a0 = r0[0], a1 = r0[1];
            float4 c0 = r1[0], c1 = r1[1];
            w2p[p][0] = pack2(a0.x, c0.x); w2p[p][1] = pack2(a0.y, c0.y);
            w2p[p][2] = pack2(a0.z, c0.z); w2p[p][3] = pack2(a0.w, c0.w);
            w2p[p][4] = pack2(a1.x, c1.x); w2p[p][5] = pack2(a1.y, c1.y);
            w2p[p][6] = pack2(a1.z, c1.z); w2p[p][7] = pack2(a1.w, c1.w);
            b2p[p] = pack2(b2[e0], b2[e0 + 1]);
        }

        // Prime all empty barriers so producer's first NSTAGE waits pass.
        #pragma unroll
        for (int s = 0; s < NSTAGE; ++s) bar_arrive(BAR_EMPTY(s), 512);

        for (int st = 0; st < nst; ++st) {
            const int s  = st & (NSTAGE - 1);
            const int t0 = start + st * GP;

            bar_sync(BAR_FULL(s), 512);   // q slot s ready

            #pragma unroll
            for (int g = 0; g < GP; ++g) {
                const int t = t0 + g;
                if (t >= end) break;
                const float4* qp = reinterpret_cast<const float4*>(
                    s_q + (s * GP + g) * FFN);
                float4 qa = qp[0], qb = qp[1];
                float qf[FFN] = {qa.x, qa.y, qa.z, qa.w, qb.x, qb.y, qb.z, qb.w};

                unsigned long long o2[4];
                #pragma unroll
                for (int p = 0; p < 4; ++p) o2[p] = b2p[p];
                #pragma unroll
                for (int f = 0; f < FFN; ++f) {
                    const unsigned long long qd = pack2(qf[f], qf[f]);
                    #pragma unroll
                    for (int p = 0; p < 4; ++p)
                        o2[p] = fma2(w2p[p][f], qd, o2[p]);
                }

                ulonglong2* o4 = reinterpret_cast<ulonglong2*>(
                    out + (size_t)t * EMBED + ct * 8);
                ulonglong2 s0; s0.x = o2[0]; s0.y = o2[1];
                ulonglong2 s1; s1.x = o2[2]; s1.y = o2[3];
                o4[0] = s0;
                o4[1] = s1;
            }

            bar_arrive(BAR_EMPTY(s), 512);  // slot s free for producer
        }
    }
}

// ---------------------------------------------------------------------------
// Launch: inputs in metadata order: x, W1, b1, W2, b2. Output float [N, EMBED].
// ---------------------------------------------------------------------------
extern "C" void kernel_launch(void* const* d_in, const int* in_sizes, int n_in,
                              void* d_out, int out_size)
{
    const float* x  = (const float*)d_in[0];
    const float* W1 = (const float*)d_in[1];
    const float* b1 = (const float*)d_in[2];
    const float* W2 = (const float*)d_in[3];
    const float* b2 = (const float*)d_in[4];
    float* out = (float*)d_out;

    const int ntok = in_sizes[0] / EMBED;

    int dev = 0;
    cudaGetDevice(&dev);
    int sms = 148;
    cudaDeviceGetAttribute(&sms, cudaDevAttrMultiProcessorCount, dev);

    static bool attr_done = false;
    if (!attr_done) {
        cudaFuncSetAttribute(qff_ws, cudaFuncAttributeMaxDynamicSharedMemorySize,
                             SMEM_BYTES);
        attr_done = true;
    }

    const int tpb = (ntok + sms - 1) / sms;

    qff_ws<<<sms, 512, SMEM_BYTES>>>(x, W1, b1, W2, b2, out, ntok, tpb);
}

// round 11
// speedup vs baseline: 1.9480x; 1.1297x over previous
#include <cuda_runtime.h>
#include <cuda_bf16.h>
#include <cstdint>

#define EMBED  2048
#define FFN    8
#define GP     8        // tokens per stage
#define XSLOTS 2        // x ring double-buffer (per-thread private cells)
#define QSLOTS 4        // q handoff ring depth (32 tokens of slack)

#define BAR_PROD     9
#define BAR_FULL(s)  (1 + (s))   // producer arrives, consumer syncs
#define BAR_EMPTY(s) (5 + (s))   // consumer arrives, producer syncs

// ---- packed f32x2 helpers ----
__device__ __forceinline__ unsigned long long fma2(unsigned long long a,
                                                   unsigned long long b,
                                                   unsigned long long c) {
    unsigned long long d;
    asm("fma.rn.f32x2 %0, %1, %2, %3;" : "=l"(d) : "l"(a), "l"(b), "l"(c));
    return d;
}
__device__ __forceinline__ unsigned long long pack2(float lo, float hi) {
    unsigned long long d;
    asm("mov.b64 %0, {%1, %2};" : "=l"(d) : "f"(lo), "f"(hi));
    return d;
}
__device__ __forceinline__ void unpack2(unsigned long long v, float& lo, float& hi) {
    asm("mov.b64 {%0, %1}, %2;" : "=f"(lo), "=f"(hi) : "l"(v));
}

__device__ __forceinline__ void bar_sync(int id, int cnt) {
    asm volatile("bar.sync %0, %1;" :: "r"(id), "r"(cnt) : "memory");
}
__device__ __forceinline__ void bar_arrive(int id, int cnt) {
    asm volatile("bar.arrive %0, %1;" :: "r"(id), "r"(cnt) : "memory");
}
__device__ __forceinline__ void cp16(uint32_t saddr, const void* gaddr) {
    asm volatile("cp.async.cg.shared.global [%0], [%1], 16;"
                 :: "r"(saddr), "l"(gaddr) : "memory");
}
__device__ __forceinline__ void cp_commit() {
    asm volatile("cp.async.commit_group;" ::: "memory");
}
__device__ __forceinline__ void cp_wait0() {
    asm volatile("cp.async.wait_group 0;" ::: "memory");
}

// smem layout (floats)
#define XRING_F  (XSLOTS * GP * EMBED)      // 32768 floats = 128 KB
#define SPART_F  (GP * 8 * FFN)             // 512
#define SQ_F     (QSLOTS * GP * FFN)        // 256
#define SMEM_F   (XRING_F + SPART_F + SQ_F + FFN)
#define SMEM_BYTES (SMEM_F * 4)

// ---------------------------------------------------------------------------
// Warp-specialized kernel: 1 block/SM, 512 threads.
//   warps 0-7  (tid 0-255):   producer — x -> gemm1 -> cos^2 -> s_q ring
//   warps 8-15 (tid 256-511): consumer — s_q ring -> gemm2 -> out
// x double-buffered through cp.async (slot cells are per-thread private:
// no barrier needed for recycling, wait_group 0 alone orders them).
// q handed off through a 4-slot smem ring with named full/empty barriers.
// ---------------------------------------------------------------------------
__global__ __launch_bounds__(512, 1)
void qff_ws(const float* __restrict__ x,
            const float* __restrict__ W1,
            const float* __restrict__ b1,
            const float* __restrict__ W2,
            const float* __restrict__ b2,
            float* __restrict__ out,
            int ntok, int tpb)
{
    extern __shared__ float smem[];
    float* xring  = smem;
    float* s_part = smem + XRING_F;
    float* s_q    = smem + XRING_F + SPART_F;
    float* s_b1   = smem + XRING_F + SPART_F + SQ_F;

    const int tid   = threadIdx.x;
    const int start = blockIdx.x * tpb;
    const int end   = min(start + tpb, ntok);
    if (start >= end) return;                       // uniform for whole block
    const int nst = (end - start + GP - 1) / GP;

    if (tid < 256) {
        // ==================== PRODUCER (warps 0-7) ====================
        const int lane = tid & 31;
        const int warp = tid >> 5;
        if (tid < FFN) s_b1[tid] = b1[tid];

        // W1 slice register-resident: w1p[f][j] packs cols tid*8+2j, +2j+1
        unsigned long long w1p[FFN][4];
        #pragma unroll
        for (int f = 0; f < FFN; ++f) {
            const ulonglong2* p = reinterpret_cast<const ulonglong2*>(
                W1 + f * EMBED + tid * 8);
            ulonglong2 a = p[0], b = p[1];
            w1p[f][0] = a.x; w1p[f][1] = a.y; w1p[f][2] = b.x; w1p[f][3] = b.y;
        }

        // This thread's byte address of its 32B cell within a token row.
        const uint32_t xr = (uint32_t)__cvta_generic_to_shared(xring) + tid * 32;

        // Prologue: prefetch stage 0 into slot 0.
        #pragma unroll
        for (int g = 0; g < GP; ++g) {
            const int t = start + g;
            if (t < end) {
                const uint32_t dst = xr + (uint32_t)(g * EMBED) * 4u;
                const float* src = x + (size_t)t * EMBED + tid * 8;
                cp16(dst, src);
                cp16(dst + 16, src + 4);
            }
        }
        cp_commit();

        for (int st = 0; st < nst; ++st) {
            const int xs = st & (XSLOTS - 1);
            const int qs = st & (QSLOTS - 1);
            const int t0 = start + st * GP;

            cp_wait0();                 // stage st's x ready (private cells)
            bar_sync(BAR_PROD, 256);    // finalize(st-1) done -> s_part reusable

            // Prefetch stage st+1 into the other slot. That slot's last
            // reader was this thread itself in iteration st-1 (program
            // order) -> no barrier required.
            {
                const int pt0  = start + (st + 1) * GP;
                const int slot = (st + 1) & (XSLOTS - 1);
                #pragma unroll
                for (int g = 0; g < GP; ++g) {
                    const int t = pt0 + g;
                    if (t < end) {
                        const uint32_t dst = xr + (uint32_t)((slot * GP + g) * EMBED) * 4u;
                        const float* src = x + (size_t)t * EMBED + tid * 8;
                        cp16(dst, src);
                        cp16(dst + 16, src + 4);
                    }
                }
                cp_commit();            // commit even if empty (wait math)
            }

            // Compute GP tokens: LDS x, 32 fma2, fold to vst[g].
            float vst[GP];
            #pragma unroll
            for (int g = 0; g < GP; ++g) {
                const ulonglong2* p = reinterpret_cast<const ulonglong2*>(
                    xring + (xs * GP + g) * EMBED + tid * 8);
                ulonglong2 a = p[0], b = p[1];
                unsigned long long xv[4] = {a.x, a.y, b.x, b.y};

                unsigned long long a2[FFN];
                #pragma unroll
                for (int f = 0; f < FFN; ++f) a2[f] = 0ull;
                #pragma unroll
                for (int j = 0; j < 4; ++j) {
                    #pragma unroll
                    for (int f = 0; f < FFN; ++f)
                        a2[f] = fma2(xv[j], w1p[f][j], a2[f]);
                }
                float acc[FFN];
                #pragma unroll
                for (int f = 0; f < FFN; ++f) {
                    float lo, hi; unpack2(a2[f], lo, hi);
                    acc[f] = lo + hi;
                }
                // transpose-reduce rounds xor1, xor2, xor4
                float v4[4];
                {
                    const bool hi = lane & 1;
                    #pragma unroll
                    for (int k = 0; k < 4; ++k) {
                        float keep = hi ? acc[k + 4] : acc[k];
                        float send = hi ? acc[k]     : acc[k + 4];
                        v4[k] = keep + __shfl_xor_sync(0xffffffffu, send, 1);
                    }
                }
                float v2[2];
                {
                    const bool hi = lane & 2;
                    #pragma unroll
                    for (int k = 0; k < 2; ++k) {
                        float keep = hi ? v4[k + 2] : v4[k];
                        float send = hi ? v4[k]     : v4[k + 2];
                        v2[k] = keep + __shfl_xor_sync(0xffffffffu, send, 2);
                    }
                }
                {
                    const bool hi = lane & 4;
                    float keep = hi ? v2[1] : v2[0];
                    float send = hi ? v2[0] : v2[1];
                    vst[g] = keep + __shfl_xor_sync(0xffffffffu, send, 4);
                }
            }

            // Finish warp reduction, stash per-warp partials.
            #pragma unroll
            for (int g = 0; g < GP; ++g) {
                float v = vst[g];
                v += __shfl_xor_sync(0xffffffffu, v, 8);
                v += __shfl_xor_sync(0xffffffffu, v, 16);
                if (lane < 8) {
                    const int f = ((lane & 1) << 2) | (lane & 2) | ((lane >> 2) & 1);
                    s_part[(g * 8 + warp) * FFN + f] = v;
                }
            }

            // q slot qs free (consumer arrived) + orders s_part for finalize.
            bar_sync(BAR_EMPTY(qs), 512);

            // Finalize: warp g finalizes token g (lane = feature).
            if (lane < FFN) {
                const int g = warp;
                const int t = t0 + g;
                if (t < end) {
                    float sum = s_b1[lane];
                    #pragma unroll
                    for (int w = 0; w < 8; ++w)
                        sum += s_part[(g * 8 + w) * FFN + lane];
                    sum = fmaxf(sum, 0.0f);
                    float c = __cosf(sum);
                    s_q[(qs * GP + g) * FFN + lane] = c * c;
                }
            }
            bar_arrive(BAR_FULL(qs), 512);
        }
    } else {
        // ==================== CONSUMER (warps 8-15) ====================
        const int ct = tid - 256;

        // W2 slice + b2 register-resident (packed pairs).
        unsigned long long w2p[4][FFN];
        unsigned long long b2p[4];
        #pragma unroll
        for (int p = 0; p < 4; ++p) {
            const int e0 = ct * 8 + 2 * p;
            const float4* r0 = reinterpret_cast<const float4*>(W2 + (size_t)e0 * FFN);
            const float4* r1 = reinterpret_cast<const float4*>(W2 + (size_t)(e0 + 1) * FFN);
            float4 a0 = r0[0], a1 = r0[1];
            float4 c0 = r1[0], c1 = r1[1];
            w2p[p][0] = pack2(a0.x, c0.x); w2p[p][1] = pack2(a0.y, c0.y);
            w2p[p][2] = pack2(a0.z, c0.z); w2p[p][3] = pack2(a0.w, c0.w);
            w2p[p][4] = pack2(a1.x, c1.x); w2p[p][5] = pack2(a1.y, c1.y);
            w2p[p][6] = pack2(a1.z, c1.z); w2p[p][7] = pack2(a1.w, c1.w);
            b2p[p] = pack2(b2[e0], b2[e0 + 1]);
        }

        // Prime all empty barriers so producer's first QSLOTS waits pass.
        #pragma unroll
        for (int s = 0; s < QSLOTS; ++s) bar_arrive(BAR_EMPTY(s), 512);

        for (int st = 0; st < nst; ++st) {
            const int qs = st & (QSLOTS - 1);
            const int t0 = start + st * GP;

            bar_sync(BAR_FULL(qs), 512);   // q slot ready

            #pragma unroll
            for (int g = 0; g < GP; ++g) {
                const int t = t0 + g;
                if (t >= end) break;
                const float4* qp = reinterpret_cast<const float4*>(
                    s_q + (qs * GP + g) * FFN);
                float4 qa = qp[0], qb = qp[1];
                float qf[FFN] = {qa.x, qa.y, qa.z, qa.w, qb.x, qb.y, qb.z, qb.w};

                unsigned long long o2[4];
                #pragma unroll
                for (int p = 0; p < 4; ++p) o2[p] = b2p[p];
                #pragma unroll
                for (int f = 0; f < FFN; ++f) {
                    const unsigned long long qd = pack2(qf[f], qf[f]);
                    #pragma unroll
                    for (int p = 0; p < 4; ++p)
                        o2[p] = fma2(w2p[p][f], qd, o2[p]);
                }

                ulonglong2* o4 = reinterpret_cast<ulonglong2*>(
                    out + (size_t)t * EMBED + ct * 8);
                ulonglong2 s0; s0.x = o2[0]; s0.y = o2[1];
                ulonglong2 s1; s1.x = o2[2]; s1.y = o2[3];
                o4[0] = s0;
                o4[1] = s1;
            }

            bar_arrive(BAR_EMPTY(qs), 512);  // slot free for producer
        }
    }
}

// ---------------------------------------------------------------------------
// Launch: inputs in metadata order: x, W1, b1, W2, b2. Output float [N, EMBED].
// ---------------------------------------------------------------------------
extern "C" void kernel_launch(void* const* d_in, const int* in_sizes, int n_in,
                              void* d_out, int out_size)
{
    const float* x  = (const float*)d_in[0];
    const float* W1 = (const float*)d_in[1];
    const float* b1 = (const float*)d_in[2];
    const float* W2 = (const float*)d_in[3];
    const float* b2 = (const float*)d_in[4];
    float* out = (float*)d_out;

    const int ntok = in_sizes[0] / EMBED;

    int dev = 0;
    cudaGetDevice(&dev);
    int sms = 148;
    cudaDeviceGetAttribute(&sms, cudaDevAttrMultiProcessorCount, dev);

    static bool attr_done = false;
    if (!attr_done) {
        cudaFuncSetAttribute(qff_ws, cudaFuncAttributeMaxDynamicSharedMemorySize,
                             SMEM_BYTES);
        attr_done = true;
    }

    const int tpb = (ntok + sms - 1) / sms;

    qff_ws<<<sms, 512, SMEM_BYTES>>>(x, W1, b1, W2, b2, out, ntok, tpb);
}